// round 7
// baseline (speedup 1.0000x reference)
#include <cuda_runtime.h>
#include <cuda_bf16.h>
#include <cstdint>

#define TT   2048
#define CC   768
#define NHH  12
#define HS   64
#define C3   2304
#define NSI  255
#define BHC  96
#define NCHUNK 16

__device__ float g_qkv[(size_t)8*TT*C3];
__device__ float g_v  [(size_t)BHC*TT*HS];
__device__ float g_kc [(size_t)BHC*TT*HS];
__device__ float g_vc [(size_t)BHC*TT*HS];
__device__ float g_part[2*BHC*NCHUNK*HS];
__device__ float g_Ki[(size_t)BHC*NSI*HS];
__device__ float g_Vi[(size_t)BHC*NSI*HS];
__device__ float g_att[(size_t)8*TT*CC];
__device__ __nv_bfloat16 g_Wvh[HS*4096];
__device__ __nv_bfloat16 g_Wvl[HS*4096];
__device__ __nv_bfloat16 g_sh[(size_t)16384*768];
__device__ __nv_bfloat16 g_sl[(size_t)16384*768];
__device__ __nv_bfloat16 g_w1h[(size_t)C3*CC], g_w1l[(size_t)C3*CC];
__device__ __nv_bfloat16 g_w2h[(size_t)CC*CC], g_w2l[(size_t)CC*CC];

// ======================= helpers ===========================================
__device__ __forceinline__ uint32_t smem_u32(const void* p) {
    uint32_t a;
    asm("{ .reg .u64 t; cvta.to.shared.u64 t, %1; cvt.u32.u64 %0, t; }"
        : "=r"(a) : "l"(p));
    return a;
}
__device__ __forceinline__ void interval_of(int s, int& l, int& r) {
    int base = 0, L = 16, n = TT / 16;
    while (s >= base + n) { base += n; n >>= 1; L <<= 1; }
    int i = s - base;
    l = i * L; r = l + L - 1;
}
__device__ __forceinline__ void mma16816(float* c, const unsigned* a, const unsigned* b) {
    asm volatile(
        "mma.sync.aligned.m16n8k16.row.col.f32.bf16.bf16.f32 "
        "{%0,%1,%2,%3}, {%4,%5,%6,%7}, {%8,%9}, {%0,%1,%2,%3};\n"
        : "+f"(c[0]), "+f"(c[1]), "+f"(c[2]), "+f"(c[3])
        : "r"(a[0]), "r"(a[1]), "r"(a[2]), "r"(a[3]), "r"(b[0]), "r"(b[1]));
}
#define LDSM4(r0, r1, r2, r3, addr) \
    asm volatile("ldmatrix.sync.aligned.m8n8.x4.shared.b16 {%0,%1,%2,%3}, [%4];" \
        : "=r"(r0), "=r"(r1), "=r"(r2), "=r"(r3) : "r"(addr))
#define CP_ASYNC16(dst, src) \
    asm volatile("cp.async.cg.shared.global [%0], [%1], 16;" :: "r"(dst), "l"(src))
#define CP_COMMIT() asm volatile("cp.async.commit_group;" ::: "memory")
#define CP_WAIT0()  asm volatile("cp.async.wait_group 0;" ::: "memory")

__device__ __forceinline__ unsigned pk2(float a, float b,
                                        __nv_bfloat16& la, __nv_bfloat16& lb) {
    __nv_bfloat16 ha = __float2bfloat16(a);
    __nv_bfloat16 hb = __float2bfloat16(b);
    la = __float2bfloat16(a - __bfloat162float(ha));
    lb = __float2bfloat16(b - __bfloat162float(hb));
    __nv_bfloat162 t; t.x = ha; t.y = hb;
    return *(unsigned*)&t;
}
__device__ __forceinline__ unsigned pkl(__nv_bfloat16 a, __nv_bfloat16 b) {
    __nv_bfloat162 t; t.x = a; t.y = b;
    return *(unsigned*)&t;
}

// ---------- fp32 -> bf16 hi/lo split ---------------------------------------
__global__ void split4_kernel(const float* __restrict__ src,
                              __nv_bfloat16* __restrict__ h,
                              __nv_bfloat16* __restrict__ l) {
    int i = (blockIdx.x * 256 + threadIdx.x) * 4;
    float4 v = *(const float4*)(src + i);
    __nv_bfloat16 l0, l1, l2, l3;
    unsigned h01 = pk2(v.x, v.y, l0, l1);
    unsigned h23 = pk2(v.z, v.w, l2, l3);
    *(unsigned*)(h + i)     = h01;
    *(unsigned*)(h + i + 2) = h23;
    *(unsigned*)(l + i)     = pkl(l0, l1);
    *(unsigned*)(l + i + 2) = pkl(l2, l3);
}
__global__ void wvsplit_kernel(const float* __restrict__ Wv) {
    int idx = blockIdx.x * 256 + threadIdx.x;
    float v = Wv[idx];
    __nv_bfloat16 h = __float2bfloat16(v);
    g_Wvh[idx] = h;
    g_Wvl[idx] = __float2bfloat16(v - __bfloat162float(h));
}

// ======================= bf16-split GEMM (cp.async + ldmatrix) =============
// C[M,N] = A[M,K] @ B[N,K]^T with pre-split bf16 hi/lo, 3-term compensation.
// 128x128 tile, kchunk 32, pitch 40 elems (ldmatrix conflict-free).
#define KC 32
#define GP 40
#define TILE_ELE (128*GP)
#define TILE_BYTES (TILE_ELE*2)
#define BUF_BYTES (4*TILE_BYTES)     // Ah,Al,Bh,Bl = 40960 B
#define G2_SMEM (2*BUF_BYTES)        // 81920 B

__device__ __forceinline__ void g2_issue(
    const __nv_bfloat16* __restrict__ Ah, const __nv_bfloat16* __restrict__ Al,
    const __nv_bfloat16* __restrict__ Bh, const __nv_bfloat16* __restrict__ Bl,
    uint32_t sbuf, int bm, int bn, int K, int kc, int tid)
{
#pragma unroll
    for (int it = 0; it < 8; it++) {
        int slot = tid + it * 256;
        int tile = slot >> 9, rem = slot & 511;
        int row = rem >> 2, q = rem & 3;
        const __nv_bfloat16* src;
        int rbase;
        if (tile == 0)      { src = Ah; rbase = bm; }
        else if (tile == 1) { src = Al; rbase = bm; }
        else if (tile == 2) { src = Bh; rbase = bn; }
        else                { src = Bl; rbase = bn; }
        const __nv_bfloat16* g = src + (size_t)(rbase + row) * K + kc * KC + q * 8;
        uint32_t d = sbuf + (uint32_t)(tile * TILE_BYTES + (row * GP + q * 8) * 2);
        CP_ASYNC16(d, g);
    }
    CP_COMMIT();
}

__global__ __launch_bounds__(256) void gemm_bf16(
    const __nv_bfloat16* __restrict__ Ah, const __nv_bfloat16* __restrict__ Al,
    const __nv_bfloat16* __restrict__ Bh, const __nv_bfloat16* __restrict__ Bl,
    float* __restrict__ C, int M, int N, int K)
{
    extern __shared__ char smraw[];
    const uint32_t s0 = smem_u32(smraw);
    const int tid = threadIdx.x;
    const int warpid = tid >> 5, lane = tid & 31;
    const int bm = blockIdx.y << 7, bn = blockIdx.x << 7;
    const int wm = (warpid >> 2) << 6;   // 0/64
    const int wn = (warpid & 3) << 5;    // 0..96
    const int lrow = lane & 15;
    const int lcol = (lane >> 4) << 3;

    float acc[16][4];
#pragma unroll
    for (int i = 0; i < 16; i++)
#pragma unroll
        for (int j = 0; j < 4; j++) acc[i][j] = 0.f;

    const int nt = K >> 5;   // 24 for K=768
    g2_issue(Ah, Al, Bh, Bl, s0, bm, bn, K, 0, tid);

    for (int kc = 0; kc < nt; kc++) {
        const uint32_t sc = s0 + (kc & 1) * BUF_BYTES;
        CP_WAIT0();
        __syncthreads();
        if (kc + 1 < nt)
            g2_issue(Ah, Al, Bh, Bl, s0 + ((kc + 1) & 1) * BUF_BYTES,
                     bm, bn, K, kc + 1, tid);

        const uint32_t aH = sc, aL = sc + TILE_BYTES;
        const uint32_t bH = sc + 2 * TILE_BYTES, bL = sc + 3 * TILE_BYTES;
#pragma unroll
        for (int ks = 0; ks < 2; ks++) {
            const int k0 = ks << 4;
            unsigned ah[4][4], al[4][4], bhf[4][2], blf[4][2];
#pragma unroll
            for (int mt = 0; mt < 4; mt++) {
                uint32_t off = (uint32_t)(((wm + mt * 16 + lrow) * GP + k0 + lcol) * 2);
                LDSM4(ah[mt][0], ah[mt][1], ah[mt][2], ah[mt][3], aH + off);
                LDSM4(al[mt][0], al[mt][1], al[mt][2], al[mt][3], aL + off);
            }
#pragma unroll
            for (int pr = 0; pr < 2; pr++) {
                uint32_t off = (uint32_t)(((wn + pr * 16 + lrow) * GP + k0 + lcol) * 2);
                unsigned t0, t1, t2, t3;
                LDSM4(t0, t1, t2, t3, bH + off);
                bhf[pr*2][0] = t0; bhf[pr*2+1][0] = t1;
                bhf[pr*2][1] = t2; bhf[pr*2+1][1] = t3;
                LDSM4(t0, t1, t2, t3, bL + off);
                blf[pr*2][0] = t0; blf[pr*2+1][0] = t1;
                blf[pr*2][1] = t2; blf[pr*2+1][1] = t3;
            }
#pragma unroll
            for (int mt = 0; mt < 4; mt++)
#pragma unroll
                for (int ntl = 0; ntl < 4; ntl++) {
                    float* cp = acc[mt*4 + ntl];
                    mma16816(cp, ah[mt], bhf[ntl]);
                    mma16816(cp, ah[mt], blf[ntl]);
                    mma16816(cp, al[mt], bhf[ntl]);
                }
        }
        __syncthreads();
    }

    const int gm = lane >> 2;
#pragma unroll
    for (int mt = 0; mt < 4; mt++) {
        int row = bm + wm + mt * 16 + gm;
        int col = bn + wn + (lane & 3) * 2;
#pragma unroll
        for (int ntl = 0; ntl < 4; ntl++) {
            float* cp = acc[mt*4 + ntl];
            *(float2*)(C + (size_t)row * N + col + ntl*8)       = make_float2(cp[0], cp[1]);
            *(float2*)(C + (size_t)(row + 8) * N + col + ntl*8) = make_float2(cp[2], cp[3]);
        }
    }
}

// ------------- fused v-einsum (mma.sync + ldmatrix inner B loads) ----------
#define SV 72
#define SKP 65
__global__ __launch_bounds__(256, 1) void veinsum_mma(const float* __restrict__ bv) {
    extern __shared__ char smraw[];
    float*         sk  = (float*)smraw;                       // [128][65]
    __nv_bfloat16* v0h = (__nv_bfloat16*)(smraw + 33280);     // [128][72]
    __nv_bfloat16* v0l = (__nv_bfloat16*)(smraw + 33280 + 18432);
    __nv_bfloat16* sB  = (__nv_bfloat16*)(smraw + 70144);     // h0,h1,l0,l1 each [64][72]

    const int tid = threadIdx.x;
    const int bh = blockIdx.y;
    const int b = bh / NHH, h = bh - b*NHH;
    const int t0 = blockIdx.x << 7;
    const int warpid = tid >> 5, lane = tid & 31;
    const int wm = (warpid >> 1) << 5;
    const int wn = (warpid & 1) << 5;
    const int gm = lane >> 2, kp = (lane & 3) << 1;
    const int lrow = lane & 15;
    const int lcol = (lane >> 4) << 3;

    const float* kbase = g_qkv + ((size_t)(b*TT + t0))*C3 + CC + h*HS;
    {
        int r = tid >> 4, c4 = (tid & 15) << 2;
#pragma unroll
        for (int p = 0; p < 8; p++) {
            int row = r + p*16;
            float4 kv = *(const float4*)(kbase + (size_t)row*C3 + c4);
            sk[row*SKP + c4+0] = kv.x; sk[row*SKP + c4+1] = kv.y;
            sk[row*SKP + c4+2] = kv.z; sk[row*SKP + c4+3] = kv.w;
            float4 vv = *(const float4*)(kbase + (size_t)row*C3 + CC + c4);
            __nv_bfloat16 l0, l1, l2, l3;
            unsigned h01 = pk2(vv.x, vv.y, l0, l1);
            unsigned h23 = pk2(vv.z, vv.w, l2, l3);
            int ro = row*SV + c4;
            *(unsigned*)(v0h + ro)     = h01;
            *(unsigned*)(v0h + ro + 2) = h23;
            *(unsigned*)(v0l + ro)     = pkl(l0, l1);
            *(unsigned*)(v0l + ro + 2) = pkl(l2, l3);
        }
    }
    uint4 pbh[2], pbl[2];
#pragma unroll
    for (int p = 0; p < 2; p++) {
        int slot = tid + p*256;
        int e = slot >> 3, q = slot & 7;
        pbh[p] = *(const uint4*)(g_Wvh + (size_t)e*4096 + q*8);
        pbl[p] = *(const uint4*)(g_Wvl + (size_t)e*4096 + q*8);
    }
    __syncthreads();

    unsigned vh[4][2][4], vl[4][2][4];
#pragma unroll
    for (int ks = 0; ks < 4; ks++) {
        int k0 = ks << 4;
#pragma unroll
        for (int mt = 0; mt < 2; mt++) {
            const __nv_bfloat16* p0 = v0h + (wm + mt*16 + gm)*SV + k0 + kp;
            const __nv_bfloat16* p1 = v0l + (wm + mt*16 + gm)*SV + k0 + kp;
            vh[ks][mt][0] = *(const unsigned*)(p0);
            vh[ks][mt][1] = *(const unsigned*)(p0 + 8*SV);
            vh[ks][mt][2] = *(const unsigned*)(p0 + 8);
            vh[ks][mt][3] = *(const unsigned*)(p0 + 8*SV + 8);
            vl[ks][mt][0] = *(const unsigned*)(p1);
            vl[ks][mt][1] = *(const unsigned*)(p1 + 8*SV);
            vl[ks][mt][2] = *(const unsigned*)(p1 + 8);
            vl[ks][mt][3] = *(const unsigned*)(p1 + 8*SV + 8);
        }
    }

    float acc[2][4][4];
#pragma unroll
    for (int mt = 0; mt < 2; mt++)
#pragma unroll
        for (int ntl = 0; ntl < 4; ntl++)
#pragma unroll
            for (int j = 0; j < 4; j++) acc[mt][ntl][j] = 0.f;

    {
        __nv_bfloat16* dBh = sB;
        __nv_bfloat16* dBl = sB + 2*64*SV;
#pragma unroll
        for (int p = 0; p < 2; p++) {
            int slot = tid + p*256;
            int e = slot >> 3, q = slot & 7;
            *(uint4*)(dBh + e*SV + q*8) = pbh[p];
            *(uint4*)(dBl + e*SV + q*8) = pbl[p];
        }
    }
    __syncthreads();

    const uint32_t sB_u = smem_u32(sB);

    for (int i = 0; i < 64; i++) {
        int cur = i & 1, nxt = cur ^ 1;
        if (i + 1 < 64) {
#pragma unroll
            for (int p = 0; p < 2; p++) {
                int slot = tid + p*256;
                int e = slot >> 3, q = slot & 7;
                pbh[p] = *(const uint4*)(g_Wvh + (size_t)e*4096 + (i+1)*64 + q*8);
                pbl[p] = *(const uint4*)(g_Wvl + (size_t)e*4096 + (i+1)*64 + q*8);
            }
        }
        const uint32_t cBh_u = sB_u + (uint32_t)(cur * 64 * SV * 2);
        const uint32_t cBl_u = sB_u + (uint32_t)((2 + cur) * 64 * SV * 2);

        float tacc[2][4][4];
#pragma unroll
        for (int mt = 0; mt < 2; mt++)
#pragma unroll
            for (int ntl = 0; ntl < 4; ntl++)
#pragma unroll
                for (int j = 0; j < 4; j++) tacc[mt][ntl][j] = 0.f;

#pragma unroll
        for (int ks = 0; ks < 4; ks++) {
            int k0 = ks << 4;
            unsigned bhf[4][2], blf[4][2];
#pragma unroll
            for (int pr = 0; pr < 2; pr++) {
                uint32_t off = (uint32_t)(((wn + pr*16 + lrow) * SV + k0 + lcol) * 2);
                unsigned t0b, t1b, t2b, t3b;
                LDSM4(t0b, t1b, t2b, t3b, cBh_u + off);
                bhf[pr*2][0] = t0b; bhf[pr*2+1][0] = t1b;
                bhf[pr*2][1] = t2b; bhf[pr*2+1][1] = t3b;
                LDSM4(t0b, t1b, t2b, t3b, cBl_u + off);
                blf[pr*2][0] = t0b; blf[pr*2+1][0] = t1b;
                blf[pr*2][1] = t2b; blf[pr*2+1][1] = t3b;
            }
#pragma unroll
            for (int mt = 0; mt < 2; mt++)
#pragma unroll
                for (int ntl = 0; ntl < 4; ntl++) {
                    float* cp = tacc[mt][ntl];
                    mma16816(cp, vh[ks][mt], bhf[ntl]);
                    mma16816(cp, vh[ks][mt], blf[ntl]);
                    mma16816(cp, vl[ks][mt], bhf[ntl]);
                }
        }
#pragma unroll
        for (int mt = 0; mt < 2; mt++) {
            float k0v = sk[(wm + mt*16 + gm)*SKP + i];
            float k1v = sk[(wm + mt*16 + gm + 8)*SKP + i];
#pragma unroll
            for (int ntl = 0; ntl < 4; ntl++) {
                acc[mt][ntl][0] += k0v * tacc[mt][ntl][0];
                acc[mt][ntl][1] += k0v * tacc[mt][ntl][1];
                acc[mt][ntl][2] += k1v * tacc[mt][ntl][2];
                acc[mt][ntl][3] += k1v * tacc[mt][ntl][3];
            }
        }
        if (i + 1 < 64) {
            __nv_bfloat16* dBh = sB + nxt*64*SV;
            __nv_bfloat16* dBl = sB + (2 + nxt)*64*SV;
#pragma unroll
            for (int p = 0; p < 2; p++) {
                int slot = tid + p*256;
                int e = slot >> 3, q = slot & 7;
                *(uint4*)(dBh + e*SV + q*8) = pbh[p];
                *(uint4*)(dBl + e*SV + q*8) = pbl[p];
            }
            __syncthreads();
        }
    }

    float* vout = g_v + ((size_t)bh*TT + t0)*HS;
    int col = wn + (lane & 3)*2;
#pragma unroll
    for (int mt = 0; mt < 2; mt++) {
        int row = wm + mt*16 + gm;
#pragma unroll
        for (int ntl = 0; ntl < 4; ntl++) {
            int c = col + ntl*8;
            float b0 = bv[c], b1 = bv[c+1];
            *(float2*)(vout + (size_t)row*HS + c) =
                make_float2(acc[mt][ntl][0] + b0, acc[mt][ntl][1] + b1);
            *(float2*)(vout + (size_t)(row+8)*HS + c) =
                make_float2(acc[mt][ntl][2] + b0, acc[mt][ntl][3] + b1);
        }
    }
}

// ---------------- cumsum / slices / attention (unchanged) ------------------
__global__ void cumsum_partial() {
    int chunk = blockIdx.x, bh = blockIdx.y, which = blockIdx.z;
    int d = threadIdx.x;
    int b = bh / NHH, h = bh - b*NHH;
    float s = 0.f;
    if (which == 0) {
        const float* p = g_qkv + ((size_t)(b*TT + (chunk<<7)))*C3 + CC + h*HS + d;
#pragma unroll 4
        for (int t2 = 0; t2 < 128; t2++) s += p[(size_t)t2*C3];
    } else {
        const float* p = g_v + ((size_t)bh*TT + (chunk<<7))*HS + d;
#pragma unroll 4
        for (int t2 = 0; t2 < 128; t2++) s += p[t2*HS];
    }
    g_part[((size_t)(which*BHC + bh)*NCHUNK + chunk)*HS + d] = s;
}

__global__ void cumsum_scanpart() {
    int bh = blockIdx.x, which = blockIdx.y;
    int d = threadIdx.x;
    float run = 0.f;
    for (int c = 0; c < NCHUNK; c++) {
        size_t idx = ((size_t)(which*BHC + bh)*NCHUNK + c)*HS + d;
        float xv = g_part[idx];
        g_part[idx] = run;
        run += xv;
    }
}

__global__ void cumsum_final() {
    int chunk = blockIdx.x, bh = blockIdx.y, which = blockIdx.z;
    int d = threadIdx.x;
    int b = bh / NHH, h = bh - b*NHH;
    float run = g_part[((size_t)(which*BHC + bh)*NCHUNK + chunk)*HS + d];
    float* outp = (which ? g_vc : g_kc) + ((size_t)bh*TT + (chunk<<7))*HS + d;
    if (which == 0) {
        const float* p = g_qkv + ((size_t)(b*TT + (chunk<<7)))*C3 + CC + h*HS + d;
#pragma unroll 4
        for (int t2 = 0; t2 < 128; t2++) { run += p[(size_t)t2*C3]; outp[(size_t)t2*HS] = run; }
    } else {
        const float* p = g_v + ((size_t)bh*TT + (chunk<<7))*HS + d;
#pragma unroll 4
        for (int t2 = 0; t2 < 128; t2++) { run += p[t2*HS]; outp[(size_t)t2*HS] = run; }
    }
}

__global__ void slices_kernel() {
    int bh = blockIdx.x;
    const float* kcb = g_kc + (size_t)bh*TT*HS;
    const float* vcb = g_vc + (size_t)bh*TT*HS;
    for (int idx = threadIdx.x; idx < NSI*HS; idx += 256) {
        int s = idx / HS, d = idx - s*HS;
        int l, r; interval_of(s, l, r);
        float kv = kcb[(size_t)r*HS + d];
        float vv = vcb[(size_t)r*HS + d];
        if (l > 0) { kv -= kcb[(size_t)(l-1)*HS + d]; vv -= vcb[(size_t)(l-1)*HS + d]; }
        g_Ki[(size_t)bh*NSI*HS + idx] = kv;
        g_Vi[(size_t)bh*NSI*HS + idx] = vv;
    }
}

__global__ __launch_bounds__(256) void attention_kernel() {
    extern __shared__ float sm[];
    float* Ks = sm;
    float* Vs = sm + NSI*HS;
    const int bh = blockIdx.y;
    const int b = bh / NHH, h = bh - b*NHH;
    const int tid = threadIdx.x;
    const int t = (blockIdx.x << 8) + tid;

    const float* Kgb = g_Ki + (size_t)bh*NSI*HS;
    const float* Vgb = g_Vi + (size_t)bh*NSI*HS;
    for (int idx = tid*4; idx < NSI*HS; idx += 1024) {
        *(float4*)(Ks + idx) = *(const float4*)(Kgb + idx);
        *(float4*)(Vs + idx) = *(const float4*)(Vgb + idx);
    }
    __syncthreads();

    float q[64];
    const float* qp = g_qkv + ((size_t)(b*TT + t))*C3 + h*HS;
#pragma unroll
    for (int d4 = 0; d4 < 16; d4++) {
        float4 qq = *(const float4*)(qp + d4*4);
        q[d4*4+0]=qq.x; q[d4*4+1]=qq.y; q[d4*4+2]=qq.z; q[d4*4+3]=qq.w;
    }
    float out[64];
#pragma unroll
    for (int d = 0; d < 64; d++) out[d] = 0.f;
    float m = -1e30f, ssum = 0.f;
    const float scale = 0.125f;
    const int twmax = t | 31;

    int sbase = 0;
#pragma unroll 1
    for (int lev = 0; lev < 8; lev++) {
        const int lsh = 4 + lev;
        const int n = TT >> lsh;
        int imaxw = (twmax + 1) >> lsh;
        if (imaxw > n) imaxw = n;
        for (int i = 0; i < imaxw; i++) {
            const int s = sbase + i;
            const int r = ((i + 1) << lsh) - 1;
            const float* Kr = Ks + s*HS;
            float a0=0.f, a1=0.f, a2=0.f, a3=0.f;
#pragma unroll
            for (int d4 = 0; d4 < 16; d4++) {
                float4 kv = *(const float4*)(Kr + d4*4);
                a0 += q[d4*4+0]*kv.x; a1 += q[d4*4+1]*kv.y;
                a2 += q[d4*4+2]*kv.z; a3 += q[d4*4+3]*kv.w;
            }
            float x = (a0+a1+a2+a3) * scale;
            if (t >= r) {
                const float* Vr = Vs + s*HS;
                if (x > m) {
                    float f = __expf(m - x);
                    ssum = ssum * f + 1.f;
                    m = x;
#pragma unroll
                    for (int d4 = 0; d4 < 16; d4++) {
                        float4 vv = *(const float4*)(Vr + d4*4);
                        out[d4*4+0] = out[d4*4+0]*f + vv.x;
                        out[d4*4+1] = out[d4*4+1]*f + vv.y;
                        out[d4*4+2] = out[d4*4+2]*f + vv.z;
                        out[d4*4+3] = out[d4*4+3]*f + vv.w;
                    }
                } else {
                    float wgt = __expf(x - m);
                    ssum += wgt;
#pragma unroll
                    for (int d4 = 0; d4 < 16; d4++) {
                        float4 vv = *(const float4*)(Vr + d4*4);
                        out[d4*4+0] += wgt*vv.x; out[d4*4+1] += wgt*vv.y;
                        out[d4*4+2] += wgt*vv.z; out[d4*4+3] += wgt*vv.w;
                    }
                }
            }
        }
        sbase += n;
    }

    const int lt = t & ~15;
    const bool hasl = lt > 0;
    const float* kr = g_kc + ((size_t)bh*TT + t)*HS;
    const float* kl = g_kc + ((size_t)bh*TT + (hasl ? lt-1 : 0))*HS;
    const float* vr = g_vc + ((size_t)bh*TT + t)*HS;
    const float* vl = g_vc + ((size_t)bh*TT + (hasl ? lt-1 : 0))*HS;
    float a0=0.f, a1=0.f, a2=0.f, a3=0.f;
#pragma unroll
    for (int d4 = 0; d4 < 16; d4++) {
        float4 kv = *(const float4*)(kr + d4*4);
        float4 klv = hasl ? *(const float4*)(kl + d4*4) : make_float4(0.f,0.f,0.f,0.f);
        a0 += q[d4*4+0]*(kv.x-klv.x); a1 += q[d4*4+1]*(kv.y-klv.y);
        a2 += q[d4*4+2]*(kv.z-klv.z); a3 += q[d4*4+3]*(kv.w-klv.w);
    }
    float xt = (a0+a1+a2+a3) * scale;
    if (xt > m) {
        float f = __expf(m - xt);
        ssum = ssum * f + 1.f;
        m = xt;
#pragma unroll
        for (int d4 = 0; d4 < 16; d4++) {
            float4 vv = *(const float4*)(vr + d4*4);
            float4 vlv = hasl ? *(const float4*)(vl + d4*4) : make_float4(0.f,0.f,0.f,0.f);
            out[d4*4+0] = out[d4*4+0]*f + (vv.x-vlv.x);
            out[d4*4+1] = out[d4*4+1]*f + (vv.y-vlv.y);
            out[d4*4+2] = out[d4*4+2]*f + (vv.z-vlv.z);
            out[d4*4+3] = out[d4*4+3]*f + (vv.w-vlv.w);
        }
    } else {
        float wgt = __expf(xt - m);
        ssum += wgt;
#pragma unroll
        for (int d4 = 0; d4 < 16; d4++) {
            float4 vv = *(const float4*)(vr + d4*4);
            float4 vlv = hasl ? *(const float4*)(vl + d4*4) : make_float4(0.f,0.f,0.f,0.f);
            out[d4*4+0] += wgt*(vv.x-vlv.x); out[d4*4+1] += wgt*(vv.y-vlv.y);
            out[d4*4+2] += wgt*(vv.z-vlv.z); out[d4*4+3] += wgt*(vv.w-vlv.w);
        }
    }

    float inv = 1.f / ssum;
    float* op = g_att + ((size_t)(b*TT + t))*CC + h*HS;
#pragma unroll
    for (int d4 = 0; d4 < 16; d4++) {
        *(float4*)(op + d4*4) = make_float4(out[d4*4+0]*inv, out[d4*4+1]*inv,
                                            out[d4*4+2]*inv, out[d4*4+3]*inv);
    }
}

extern "C" void kernel_launch(void* const* d_in, const int* in_sizes, int n_in,
                              void* d_out, int out_size) {
    (void)in_sizes; (void)n_in; (void)out_size;
    const float* x     = (const float*)d_in[0];
    const float* Wqkv  = (const float*)d_in[1];
    const float* Wproj = (const float*)d_in[2];
    const float* Wv    = (const float*)d_in[3];
    const float* bv    = (const float*)d_in[4];
    float* out = (float*)d_out;

    static bool attr_set = false;
    if (!attr_set) {
        cudaFuncSetAttribute(gemm_bf16,
            cudaFuncAttributeMaxDynamicSharedMemorySize, G2_SMEM);
        cudaFuncSetAttribute(veinsum_mma,
            cudaFuncAttributeMaxDynamicSharedMemorySize, 107008);
        cudaFuncSetAttribute(attention_kernel,
            cudaFuncAttributeMaxDynamicSharedMemorySize, 130560);
        attr_set = true;
    }

    float* qkv;  cudaGetSymbolAddress((void**)&qkv, g_qkv);
    float* gatt; cudaGetSymbolAddress((void**)&gatt, g_att);
    __nv_bfloat16 *sh, *sl, *w1h, *w1l, *w2h, *w2l;
    cudaGetSymbolAddress((void**)&sh,  g_sh);
    cudaGetSymbolAddress((void**)&sl,  g_sl);
    cudaGetSymbolAddress((void**)&w1h, g_w1h);
    cudaGetSymbolAddress((void**)&w1l, g_w1l);
    cudaGetSymbolAddress((void**)&w2h, g_w2h);
    cudaGetSymbolAddress((void**)&w2l, g_w2l);

    // 0. splits
    split4_kernel<<<12288, 256>>>(x, sh, sl);
    split4_kernel<<<1728, 256>>>(Wqkv, w1h, w1l);
    split4_kernel<<<576, 256>>>(Wproj, w2h, w2l);
    wvsplit_kernel<<<1024, 256>>>(Wv);

    // 1. QKV GEMM: (16384,768) @ (2304,768)^T
    gemm_bf16<<<dim3(18, 128), 256, G2_SMEM>>>(sh, sl, w1h, w1l, qkv, 16384, 2304, 768);

    // 2. fused v-einsum
    veinsum_mma<<<dim3(16, BHC), 256, 107008>>>(bv);

    // 3. cumsum
    cumsum_partial <<<dim3(NCHUNK, BHC, 2), 64>>>();
    cumsum_scanpart<<<dim3(BHC, 2), 64>>>();
    cumsum_final   <<<dim3(NCHUNK, BHC, 2), 64>>>();

    // 4. interval slices
    slices_kernel<<<BHC, 256>>>();

    // 5. attention
    attention_kernel<<<dim3(8, BHC), 256, 130560>>>();

    // 6. split attention output, then proj GEMM
    split4_kernel<<<12288, 256>>>(gatt, sh, sl);
    gemm_bf16<<<dim3(6, 128), 256, G2_SMEM>>>(sh, sl, w2h, w2l, out, 16384, 768, 768);
}